// round 4
// baseline (speedup 1.0000x reference)
#include <cuda_runtime.h>
#include <cstdint>

#define N_IN    6
#define N_MF    4
#define N_RULES 4096
#define BATCH   4096
#define BT      32
#define NWARPS  32
#define NTHREADS 1024
#define NBLOCKS (BATCH / BT)     // 128

// smem layout (floats)
#define CS_F   (2048 * 16)       // coeff, pair-interleaved: 128 KB
#define QP_F   (32 * BT * 2)     // packed Q pairs, [m][lane] u64: 8 KB
#define MSH_F  (12 * BT)         // memberships inputs 0..2: [i*4+k][lane]
#define XR_F   (7 * BT)          // xi[0..5] + rden, [j][lane]
#define ACC_F  (NWARPS * 7 * BT) // per-warp partials: 28 KB
#define SMEM_BYTES ((CS_F + QP_F + MSH_F + XR_F + ACC_F) * 4)

__device__ __forceinline__ uint32_t s2u(const void* p) {
    return (uint32_t)__cvta_generic_to_shared(p);
}
__device__ __forceinline__ unsigned long long pk2(float lo, float hi) {
    unsigned long long r;
    asm("mov.b64 %0, {%1, %2};" : "=l"(r) : "f"(lo), "f"(hi));
    return r;
}

__global__ void __launch_bounds__(NTHREADS, 1) anfis_fused_kernel(
    const float* __restrict__ x, const float* __restrict__ a,
    const float* __restrict__ b, const float* __restrict__ c,
    const float* __restrict__ coeff, float* __restrict__ out)
{
    extern __shared__ float smem[];
    float* Cs    = smem;             // pair p: [j0r0,j0r1,...,j6r0,j6r1,pad,pad]
    float* Qpsh  = Cs + CS_F;        // u64 per (m, lane)
    float* msh   = Qpsh + QP_F;
    float* xrsh  = msh + MSH_F;
    float* accsh = xrsh + XR_F;

    const int tid  = threadIdx.x;
    const int lane = tid & 31;
    const int wid  = tid >> 5;
    const int b0   = blockIdx.x * BT;

    // ---- Stage coeff (linear coalesced LDG, scattered STS) ----
    // float idx -> rule r = idx/7, j = idx%7 ; pair p = r>>1, slot = r&1
    #pragma unroll
    for (int it = 0; it < (N_RULES * 7) / NTHREADS; it++) {
        int idx = it * NTHREADS + tid;
        float v = __ldg(&coeff[idx]);
        int r = idx / 7;
        int j = idx - r * 7;
        Cs[(r >> 1) * 16 + j * 2 + (r & 1)] = v;
    }

    // ---- Phase 1 (warps 0 & 1 only): memberships, tables ----
    if (wid < 2) {
        const int bb = b0 + lane;
        float xi[N_IN];
        float mm[N_IN][N_MF];
        float den = 1.0f;
        #pragma unroll
        for (int i = 0; i < N_IN; i++) {
            xi[i] = __ldg(&x[bb * N_IN + i]);
            float s = 0.0f;
            #pragma unroll
            for (int k = 0; k < N_MF; k++) {
                float av = __ldg(&a[i * N_MF + k]);
                float bv = __ldg(&b[i * N_MF + k]);
                float cv = __ldg(&c[i * N_MF + k]);
                float d  = (xi[i] - cv) / av;
                float d2 = d * d;
                float db = (bv == 2.0f) ? (d2 * d2) : __powf(d2, bv);
                float mv = 1.0f / (1.0f + db);
                mm[i][k] = mv;
                s += mv;
            }
            den *= s;
        }
        if (wid == 0) {
            // memberships of inputs 0..2 (indexed at runtime by rhi digits)
            #pragma unroll
            for (int i = 0; i < 3; i++)
                #pragma unroll
                for (int k = 0; k < N_MF; k++)
                    msh[(i * N_MF + k) * BT + lane] = mm[i][k];
            #pragma unroll
            for (int j = 0; j < 6; j++)
                xrsh[j * BT + lane] = xi[j];
            xrsh[6 * BT + lane] = 1.0f / fmaxf(den, 1e-12f);
        } else {
            // packed Q pairs: Qp[m] = (Q[2m], Q[2m+1]), m = 2*ab + half
            unsigned long long m5p0 = pk2(mm[5][0], mm[5][1]);
            unsigned long long m5p1 = pk2(mm[5][2], mm[5][3]);
            const uint32_t qb = s2u(Qpsh) + lane * 8;
            #pragma unroll
            for (int ab = 0; ab < 16; ab++) {
                float tt = mm[3][ab >> 2] * mm[4][ab & 3];
                unsigned long long ttp = pk2(tt, tt);
                unsigned long long q0, q1;
                asm("mul.rn.f32x2 %0, %1, %2;" : "=l"(q0) : "l"(ttp), "l"(m5p0));
                asm("mul.rn.f32x2 %0, %1, %2;" : "=l"(q1) : "l"(ttp), "l"(m5p1));
                asm volatile("st.shared.u64 [%0], %1;" :: "r"(qb + (2 * ab) * 256), "l"(q0));
                asm volatile("st.shared.u64 [%0], %1;" :: "r"(qb + (2 * ab + 1) * 256), "l"(q1));
            }
        }
    }
    __syncthreads();

    // ---- Phase 2: warp covers rhi = {2w, 2w+1}, 32 pairs each; 13 issues/pair ----
    unsigned long long acc[7];
    #pragma unroll
    for (int j = 0; j < 7; j++) acc[j] = 0ull;

    const uint32_t csb = s2u(Cs);
    const uint32_t qsb = s2u(Qpsh) + lane * 8;

    #pragma unroll
    for (int hh = 0; hh < 2; hh++) {
        const int rhi = 2 * wid + hh;
        const float Pv = msh[(0 * N_MF + ((rhi >> 4) & 3)) * BT + lane]
                       * msh[(1 * N_MF + ((rhi >> 2) & 3)) * BT + lane]
                       * msh[(2 * N_MF + (rhi & 3)) * BT + lane];
        const unsigned long long PP = pk2(Pv, Pv);
        const uint32_t cb = csb + (uint32_t)rhi * 2048;
        #pragma unroll
        for (int m = 0; m < 32; m++) {
            unsigned long long q, ww, c0, c1, c2, c3, c4, c5, c6;
            asm("ld.shared.u64 %0, [%1];" : "=l"(q) : "r"(qsb + m * 256));
            const uint32_t ca = cb + m * 64;
            asm("ld.shared.v2.u64 {%0, %1}, [%2];"    : "=l"(c0), "=l"(c1) : "r"(ca));
            asm("ld.shared.v2.u64 {%0, %1}, [%2+16];" : "=l"(c2), "=l"(c3) : "r"(ca));
            asm("ld.shared.v2.u64 {%0, %1}, [%2+32];" : "=l"(c4), "=l"(c5) : "r"(ca));
            asm("ld.shared.u64 %0, [%1+48];"          : "=l"(c6)           : "r"(ca));
            asm("mul.rn.f32x2 %0, %1, %2;" : "=l"(ww) : "l"(PP), "l"(q));
            asm("fma.rn.f32x2 %0, %1, %2, %0;" : "+l"(acc[0]) : "l"(ww), "l"(c0));
            asm("fma.rn.f32x2 %0, %1, %2, %0;" : "+l"(acc[1]) : "l"(ww), "l"(c1));
            asm("fma.rn.f32x2 %0, %1, %2, %0;" : "+l"(acc[2]) : "l"(ww), "l"(c2));
            asm("fma.rn.f32x2 %0, %1, %2, %0;" : "+l"(acc[3]) : "l"(ww), "l"(c3));
            asm("fma.rn.f32x2 %0, %1, %2, %0;" : "+l"(acc[4]) : "l"(ww), "l"(c4));
            asm("fma.rn.f32x2 %0, %1, %2, %0;" : "+l"(acc[5]) : "l"(ww), "l"(c5));
            asm("fma.rn.f32x2 %0, %1, %2, %0;" : "+l"(acc[6]) : "l"(ww), "l"(c6));
        }
    }

    // fold even/odd rule halves, stash per-warp partials
    #pragma unroll
    for (int j = 0; j < 7; j++) {
        float e, o;
        asm("mov.b64 {%0, %1}, %2;" : "=f"(e), "=f"(o) : "l"(acc[j]));
        accsh[(wid * 7 + j) * BT + lane] = e + o;
    }
    __syncthreads();

    // ---- Phase 3 (warp 0): reduce 32 warps, TSK dot, normalize ----
    if (wid == 0) {
        float num = 0.0f;
        #pragma unroll
        for (int j = 0; j < 7; j++) {
            float D = 0.0f;
            #pragma unroll
            for (int w = 0; w < NWARPS; w++)
                D += accsh[(w * 7 + j) * BT + lane];
            float xp = (j < 6) ? xrsh[j * BT + lane] : 1.0f;
            num = fmaf(xp, D, num);
        }
        out[b0 + lane] = num * xrsh[6 * BT + lane];
    }
}

extern "C" void kernel_launch(void* const* d_in, const int* in_sizes, int n_in,
                              void* d_out, int out_size) {
    const float* x     = (const float*)d_in[0];
    const float* a     = (const float*)d_in[1];
    const float* b     = (const float*)d_in[2];
    const float* c     = (const float*)d_in[3];
    const float* coeff = (const float*)d_in[4];
    // d_in[5] = mf_indices: full itertools.product enumeration; digit decode is analytic.
    float* out = (float*)d_out;

    static bool attr_set = false;
    if (!attr_set) {
        cudaFuncSetAttribute(anfis_fused_kernel,
                             cudaFuncAttributeMaxDynamicSharedMemorySize, SMEM_BYTES);
        attr_set = true;
    }
    anfis_fused_kernel<<<NBLOCKS, NTHREADS, SMEM_BYTES>>>(x, a, b, c, coeff, out);
}

// round 5
// speedup vs baseline: 1.3249x; 1.3249x over previous
#include <cuda_runtime.h>
#include <cstdint>

#define N_IN    6
#define N_MF    4
#define N_RULES 4096
#define BATCH   4096
#define BT      32
#define NWARPS  16
#define NTHREADS 512
#define NBLOCKS (BATCH / BT)     // 128

// smem: Cs (2048 pairs * 16 floats = 128KB) + accsh (16*7*32 = 14KB)
#define CS_F   (2048 * 16)
#define ACC_F  (NWARPS * 7 * BT)
#define SMEM_BYTES ((CS_F + ACC_F) * 4)

__device__ __forceinline__ unsigned long long pk2(float lo, float hi) {
    unsigned long long r;
    asm("mov.b64 %0, {%1, %2};" : "=l"(r) : "f"(lo), "f"(hi));
    return r;
}
__device__ __forceinline__ unsigned long long mul2(unsigned long long a, unsigned long long b) {
    unsigned long long r;
    asm("mul.rn.f32x2 %0, %1, %2;" : "=l"(r) : "l"(a), "l"(b));
    return r;
}
__device__ __forceinline__ void fma2(unsigned long long& acc, unsigned long long a, unsigned long long b) {
    asm("fma.rn.f32x2 %0, %1, %2, %0;" : "+l"(acc) : "l"(a), "l"(b));
}
// 4-way select, compiles to ISETP+SEL (no dynamic register indexing)
__device__ __forceinline__ float sel4(float v0, float v1, float v2, float v3, int d) {
    float lo = (d == 0) ? v0 : v1;
    float hi = (d == 2) ? v2 : v3;
    return (d < 2) ? lo : hi;
}

__global__ void __launch_bounds__(NTHREADS, 1) anfis_fused_kernel(
    const float* __restrict__ x, const float* __restrict__ a,
    const float* __restrict__ b, const float* __restrict__ c,
    const float* __restrict__ coeff, float* __restrict__ out)
{
    extern __shared__ float smem[];
    float* Cs    = smem;             // pair p: [j0r0,j0r1,...,j6r0,j6r1,pad,pad]
    float* accsh = Cs + CS_F;        // [warp][j][lane]

    const int tid  = threadIdx.x;
    const int lane = tid & 31;
    const int wid  = tid >> 5;
    const int b0   = blockIdx.x * BT;
    const int bb   = b0 + lane;

    // ---- Stage coeff (coalesced LDG, pair-interleaved STS) ----
    #pragma unroll
    for (int it = 0; it < (N_RULES * 7) / NTHREADS; it++) {
        int idx = it * NTHREADS + tid;
        float v = __ldg(&coeff[idx]);
        int r = idx / 7;
        int j = idx - r * 7;
        Cs[(r >> 1) * 16 + j * 2 + (r & 1)] = v;
    }

    // ---- Phase 1: every warp computes memberships for its 32 batch lanes ----
    float mm[N_IN][N_MF];
    float den = 1.0f;
    #pragma unroll
    for (int i = 0; i < N_IN; i++) {
        float xi = __ldg(&x[bb * N_IN + i]);
        float s = 0.0f;
        #pragma unroll
        for (int k = 0; k < N_MF; k++) {
            float av = __ldg(&a[i * N_MF + k]);
            float bv = __ldg(&b[i * N_MF + k]);
            float cv = __ldg(&c[i * N_MF + k]);
            float d  = (xi - cv) / av;
            float d2 = d * d;
            float db = (bv == 2.0f) ? (d2 * d2) : __powf(d2, bv);
            float mv = 1.0f / (1.0f + db);
            mm[i][k] = mv;
            s += mv;
        }
        den *= s;
    }
    const float rden = 1.0f / fmaxf(den, 1e-12f);

    // packed Q pairs in registers: Qp[m] = (Q[2m], Q[2m+1])
    unsigned long long Qp[32];
    {
        unsigned long long m5p0 = pk2(mm[5][0], mm[5][1]);
        unsigned long long m5p1 = pk2(mm[5][2], mm[5][3]);
        #pragma unroll
        for (int ab = 0; ab < 16; ab++) {
            float tt = mm[3][ab >> 2] * mm[4][ab & 3];
            unsigned long long ttp = pk2(tt, tt);
            Qp[2 * ab]     = mul2(ttp, m5p0);
            Qp[2 * ab + 1] = mul2(ttp, m5p1);
        }
    }
    __syncthreads();

    // ---- Phase 2: 4 rhi groups x 32 pairs; loads in C so ptxas pipelines ----
    unsigned long long acc[7];
    #pragma unroll
    for (int j = 0; j < 7; j++) acc[j] = 0ull;

    #pragma unroll 1
    for (int hh = 0; hh < 4; hh++) {
        const int rhi = wid * 4 + hh;
        const float Pv = sel4(mm[0][0], mm[0][1], mm[0][2], mm[0][3], (rhi >> 4) & 3)
                       * sel4(mm[1][0], mm[1][1], mm[1][2], mm[1][3], (rhi >> 2) & 3)
                       * sel4(mm[2][0], mm[2][1], mm[2][2], mm[2][3], rhi & 3);
        const unsigned long long PP = pk2(Pv, Pv);
        const ulonglong2* __restrict__ Cp =
            reinterpret_cast<const ulonglong2*>(Cs + (size_t)rhi * 512);
        #pragma unroll
        for (int m = 0; m < 32; m++) {
            ulonglong2 v0 = Cp[4 * m + 0];   // c(j0,j1)
            ulonglong2 v1 = Cp[4 * m + 1];   // c(j2,j3)
            ulonglong2 v2 = Cp[4 * m + 2];   // c(j4,j5)
            unsigned long long c6 = reinterpret_cast<const unsigned long long*>(Cp)[8 * m + 6];
            unsigned long long ww = mul2(PP, Qp[m]);
            fma2(acc[0], ww, v0.x);
            fma2(acc[1], ww, v0.y);
            fma2(acc[2], ww, v1.x);
            fma2(acc[3], ww, v1.y);
            fma2(acc[4], ww, v2.x);
            fma2(acc[5], ww, v2.y);
            fma2(acc[6], ww, c6);
        }
    }

    // fold even/odd rule halves, stash per-warp partials
    #pragma unroll
    for (int j = 0; j < 7; j++) {
        float e, o;
        asm("mov.b64 {%0, %1}, %2;" : "=f"(e), "=f"(o) : "l"(acc[j]));
        accsh[(wid * 7 + j) * BT + lane] = e + o;
    }
    __syncthreads();

    // ---- Phase 3 (warp 0): reduce 16 warps, TSK dot, normalize ----
    if (wid == 0) {
        float num = 0.0f;
        #pragma unroll
        for (int j = 0; j < 7; j++) {
            float D = 0.0f;
            #pragma unroll
            for (int w = 0; w < NWARPS; w++)
                D += accsh[(w * 7 + j) * BT + lane];
            float xp = (j < 6) ? __ldg(&x[bb * N_IN + j]) : 1.0f;
            num = fmaf(xp, D, num);
        }
        out[bb] = num * rden;
    }
}

extern "C" void kernel_launch(void* const* d_in, const int* in_sizes, int n_in,
                              void* d_out, int out_size) {
    const float* x     = (const float*)d_in[0];
    const float* a     = (const float*)d_in[1];
    const float* b     = (const float*)d_in[2];
    const float* c     = (const float*)d_in[3];
    const float* coeff = (const float*)d_in[4];
    // d_in[5] = mf_indices: full itertools.product enumeration; digit decode is analytic.
    float* out = (float*)d_out;

    static bool attr_set = false;
    if (!attr_set) {
        cudaFuncSetAttribute(anfis_fused_kernel,
                             cudaFuncAttributeMaxDynamicSharedMemorySize, SMEM_BYTES);
        attr_set = true;
    }
    anfis_fused_kernel<<<NBLOCKS, NTHREADS, SMEM_BYTES>>>(x, a, b, c, coeff, out);
}